// round 12
// baseline (speedup 1.0000x reference)
#include <cuda_runtime.h>
#include <math.h>

// Shapes fixed by the problem instance
#define KB    4
#define CIN   8
#define COUT  64
#define NLEN  4096
#define NROWS (KB * CIN)      // 32 input rows
#define SPLIT 4               // DFT blocks per input row
#define NDFT  (NROWS * SPLIT) // 128 DFT blocks
#define NTAB  16              // table blocks
#define NB    (KB * COUT)     // 256 output rows
#define NBLK  256             // total grid == NB (all co-resident)
#define TWO_PI_OVER_N 0.0015339807878856412f   // 2*pi/4096

// Scratch
__device__ float g_part_r[NROWS][SPLIT];
__device__ float g_part_i[NROWS][SPLIT];
__device__ float g_Gr[NB];
__device__ float g_Gi[NB];
__device__ float g_cos[NLEN];
__device__ float g_sin[NLEN];
__device__ int   g_count = 0;
__device__ int   g_flag  = 0;   // generation counter (sense-reversal)

__global__ __launch_bounds__(256) void fused_kernel(
    const float* __restrict__ zr, const float* __restrict__ zi,
    const float* __restrict__ A, const float* __restrict__ beta,
    const float* __restrict__ bias, const int* __restrict__ mptr,
    float* __restrict__ out)
{
    const int tid = threadIdx.x;
    const int bx  = blockIdx.x;

    __shared__ int   s_init, s_last;
    __shared__ float swr[8], swi[8];
    __shared__ float sZr[NROWS], sZi[NROWS];

    if (tid == 0) {
        s_init = *((volatile int*)&g_flag);   // generation at entry (pre-release)
        s_last = 0;
    }
    __syncthreads();

    const int m = *mptr;

    // ---------------- Phase A ----------------
    if (bx < NDFT) {
        // Partial DFT: row b, quarter 'split', 4 consecutive samples per thread.
        const int b     = bx >> 2;
        const int split = bx & 3;
        const int base  = split * 1024 + tid * 4;

        const float4 x4 = *reinterpret_cast<const float4*>(zr + (size_t)b * NLEN + base);
        const float4 y4 = *reinterpret_cast<const float4*>(zi + (size_t)b * NLEN + base);
        const float xs[4] = {x4.x, x4.y, x4.z, x4.w};
        const float ys[4] = {y4.x, y4.y, y4.z, y4.w};

        float ar = 0.f, ai = 0.f;
#pragma unroll
        for (int j = 0; j < 4; j++) {
            const int p = (m * (base + j)) & (NLEN - 1);   // exact phase index
            float s, c;
            __sincosf(TWO_PI_OVER_N * (float)p, &s, &c);
            ar += xs[j] * c - ys[j] * s;                    // e^{+i*omega*t} * z
            ai += xs[j] * s + ys[j] * c;
        }
#pragma unroll
        for (int off = 16; off > 0; off >>= 1) {
            ar += __shfl_down_sync(0xffffffff, ar, off);
            ai += __shfl_down_sync(0xffffffff, ai, off);
        }
        if ((tid & 31) == 0) { swr[tid >> 5] = ar; swi[tid >> 5] = ai; }
        __syncthreads();
        if (tid == 0) {
            float tr = 0.f, ti = 0.f;
#pragma unroll
            for (int w = 0; w < 8; w++) { tr += swr[w]; ti += swi[w]; }
            g_part_r[b][split] = tr;
            g_part_i[b][split] = ti;
        }
    } else if (bx < NDFT + NTAB) {
        // Phase table: components of e^{i*omega*mu}, exact arg reduction.
        const int mu = (bx - NDFT) * 256 + tid;
        const int p  = (m * mu) & (NLEN - 1);
        float s, c;
        __sincosf(TWO_PI_OVER_N * (float)p, &s, &c);
        g_cos[mu] = c;
        g_sin[mu] = s;
    }

    // ---------------- Grid barrier (arrival) ----------------
    __syncthreads();
    if (tid == 0) {
        __threadfence();                       // publish partials / table
        int old = atomicAdd(&g_count, 1);
        if (old == NBLK - 1) {
            s_last = 1;
            atomicExch(&g_count, 0);           // reset for next graph replay
        }
    }
    __syncthreads();

    if (s_last) {
        // -------- Last arriver: reduce partials -> gated G[256] --------
        __threadfence();
        if (tid < NROWS) {
            float tr = 0.f, ti = 0.f;
#pragma unroll
            for (int sp = 0; sp < SPLIT; sp++) {
                tr += g_part_r[tid][sp];
                ti += g_part_i[tid][sp];
            }
            sZr[tid] = tr;
            sZi[tid] = ti;
        }
        __syncthreads();

        const int k  = tid >> 6;               // one thread per (k,co)
        const int co = tid & 63;
        float Gr = 0.f, Gi = 0.f;
#pragma unroll
        for (int ci = 0; ci < CIN; ci++) {
            const float a = fabsf(A[co * CIN + ci]);
            float sb, cb;
            __sincosf(beta[co * CIN + ci], &sb, &cb);
            const float Wr = a * cb, Wi = a * sb;
            const float Zr = sZr[k * CIN + ci];
            const float Zi = sZi[k * CIN + ci];
            Gr += Wr * Zr - Wi * Zi;
            Gi += Wr * Zi + Wi * Zr;
        }
        const float mag  = sqrtf(Gr * Gr + Gi * Gi);
        const float gate = (1.f / (1.f + __expf(-(mag + bias[co])))) / (mag + 1e-5f);
        g_Gr[tid] = gate * Gr;
        g_Gi[tid] = gate * Gi;
        __syncthreads();
        if (tid == 0) {
            __threadfence();                   // publish G before releasing
            atomicAdd(&g_flag, 1);
        }
    } else if (tid == 0) {
        // -------- Everyone else: throttled spin until G is published --------
        while (*((volatile int*)&g_flag) == s_init) { __nanosleep(32); }
    }
    __syncthreads();
    __threadfence();                            // acquire G

    // ---------------- Phase B: stream the output ----------------
    // block -> output row b. out_r = Gr*c + Gi*s ; out_i = Gi*c - Gr*s.
    const int b    = bx;
    const float gr = g_Gr[b];
    const float gi = g_Gi[b];

    float* outr = out + (size_t)b * NLEN;
    float* outi = out + (size_t)NB * NLEN + (size_t)b * NLEN;

#pragma unroll
    for (int j = 0; j < 4; j++) {
        const int mu0 = j * 1024 + tid * 4;
        const float4 c4 = *reinterpret_cast<const float4*>(&g_cos[mu0]);
        const float4 s4 = *reinterpret_cast<const float4*>(&g_sin[mu0]);

        float4 vr, vi;
        vr.x = gr * c4.x + gi * s4.x;  vi.x = gi * c4.x - gr * s4.x;
        vr.y = gr * c4.y + gi * s4.y;  vi.y = gi * c4.y - gr * s4.y;
        vr.z = gr * c4.z + gi * s4.z;  vi.z = gi * c4.z - gr * s4.z;
        vr.w = gr * c4.w + gi * s4.w;  vi.w = gi * c4.w - gr * s4.w;

        *reinterpret_cast<float4*>(outr + mu0) = vr;
        *reinterpret_cast<float4*>(outi + mu0) = vi;
    }
}

extern "C" void kernel_launch(void* const* d_in, const int* in_sizes, int n_in,
                              void* d_out, int out_size)
{
    const float* z_real = (const float*)d_in[0];
    const float* z_imag = (const float*)d_in[1];
    const float* A      = (const float*)d_in[2];
    const float* beta   = (const float*)d_in[3];
    const float* bias   = (const float*)d_in[4];
    const int*   mptr   = (const int*)d_in[5];
    float* out = (float*)d_out;

    fused_kernel<<<NBLK, 256>>>(z_real, z_imag, A, beta, bias, mptr, out);
}

// round 13
// speedup vs baseline: 1.2994x; 1.2994x over previous
#include <cuda_runtime.h>
#include <math.h>

// Shapes fixed by the problem instance
#define KB    4
#define CIN   8
#define COUT  64
#define NLEN  4096
#define NROWS (KB * CIN)      // 32 input rows
#define SPLIT 2               // DFT blocks per input row (half-rows)
#define NDFT  (NROWS * SPLIT) // 64 DFT blocks
#define NTAB  16              // table blocks
#define NB    (KB * COUT)     // 256 output rows
#define NBLK  256             // total grid == NB (all co-resident)
#define TWO_PI_OVER_N 0.0015339807878856412f   // 2*pi/4096

// Scratch
__device__ float g_part_r[NROWS][SPLIT];
__device__ float g_part_i[NROWS][SPLIT];
__device__ float g_Gr[NB];
__device__ float g_Gi[NB];
__device__ float g_cos[NLEN];
__device__ float g_sin[NLEN];
__device__ int   g_count = 0;
__device__ int   g_flag  = 0;   // generation counter (sense-reversal)

__global__ __launch_bounds__(256) void fused_kernel(
    const float* __restrict__ zr, const float* __restrict__ zi,
    const float* __restrict__ A, const float* __restrict__ beta,
    const float* __restrict__ bias, const int* __restrict__ mptr,
    float* __restrict__ out)
{
    const int tid = threadIdx.x;
    const int bx  = blockIdx.x;

    __shared__ int   s_init, s_last;
    __shared__ float swr[8], swi[8];
    __shared__ float sZr[NROWS], sZi[NROWS];

    if (tid == 0) {
        s_init = *((volatile int*)&g_flag);   // generation at entry (pre-release)
        s_last = 0;
    }
    __syncthreads();

    const int m = *mptr;

    // ---------------- Phase A ----------------
    if (bx < NDFT) {
        // Partial DFT: row b, half 'split', 8 consecutive samples per thread.
        // Phase via recurrence: 2 sincosf + 7 rotations instead of 8 sincosf
        // (MUFU is the chip-wide wall: rt=8/SMSP).
        const int b     = bx >> 1;
        const int split = bx & 1;
        const int base  = split * 2048 + tid * 8;
        const float* pr = zr + (size_t)b * NLEN + base;
        const float* pi = zi + (size_t)b * NLEN + base;

        const float4 xa = *reinterpret_cast<const float4*>(pr);
        const float4 xb = *reinterpret_cast<const float4*>(pr + 4);
        const float4 ya = *reinterpret_cast<const float4*>(pi);
        const float4 yb = *reinterpret_cast<const float4*>(pi + 4);
        const float xs[8] = {xa.x, xa.y, xa.z, xa.w, xb.x, xb.y, xb.z, xb.w};
        const float ys[8] = {ya.x, ya.y, ya.z, ya.w, yb.x, yb.y, yb.z, yb.w};

        // Start phasor e^{i*omega*base} (exact index) and step e^{i*omega}.
        float s0, c0, s1, c1;
        {
            const int p0 = (m * base) & (NLEN - 1);
            __sincosf(TWO_PI_OVER_N * (float)p0, &s0, &c0);
            const int p1 = m & (NLEN - 1);
            __sincosf(TWO_PI_OVER_N * (float)p1, &s1, &c1);
        }

        float ar = 0.f, ai = 0.f;
        float c = c0, s = s0;
#pragma unroll
        for (int j = 0; j < 8; j++) {
            ar += xs[j] * c - ys[j] * s;       // e^{+i*omega*t} * z
            ai += xs[j] * s + ys[j] * c;
            const float cn = c * c1 - s * s1;  // rotate by e^{i*omega}
            const float sn = c * s1 + s * c1;
            c = cn; s = sn;
        }

#pragma unroll
        for (int off = 16; off > 0; off >>= 1) {
            ar += __shfl_down_sync(0xffffffff, ar, off);
            ai += __shfl_down_sync(0xffffffff, ai, off);
        }
        if ((tid & 31) == 0) { swr[tid >> 5] = ar; swi[tid >> 5] = ai; }
        __syncthreads();
        if (tid == 0) {
            float tr = 0.f, ti = 0.f;
#pragma unroll
            for (int w = 0; w < 8; w++) { tr += swr[w]; ti += swi[w]; }
            g_part_r[b][split] = tr;
            g_part_i[b][split] = ti;
        }
    } else if (bx < NDFT + NTAB) {
        // Phase table: components of e^{i*omega*mu}, exact arg reduction.
        const int mu = (bx - NDFT) * 256 + tid;
        const int p  = (m * mu) & (NLEN - 1);
        float s, c;
        __sincosf(TWO_PI_OVER_N * (float)p, &s, &c);
        g_cos[mu] = c;
        g_sin[mu] = s;
    }

    // ---------------- Grid barrier (arrival) ----------------
    __syncthreads();
    if (tid == 0) {
        __threadfence();                       // publish partials / table
        int old = atomicAdd(&g_count, 1);
        if (old == NBLK - 1) {
            s_last = 1;
            atomicExch(&g_count, 0);           // reset for next graph replay
        }
    }
    __syncthreads();

    if (s_last) {
        // -------- Last arriver: reduce partials -> gated G[256] --------
        __threadfence();
        if (tid < NROWS) {
            float tr = 0.f, ti = 0.f;
#pragma unroll
            for (int sp = 0; sp < SPLIT; sp++) {
                tr += g_part_r[tid][sp];
                ti += g_part_i[tid][sp];
            }
            sZr[tid] = tr;
            sZi[tid] = ti;
        }
        __syncthreads();

        const int k  = tid >> 6;               // one thread per (k,co)
        const int co = tid & 63;
        float Gr = 0.f, Gi = 0.f;
#pragma unroll
        for (int ci = 0; ci < CIN; ci++) {
            const float a = fabsf(A[co * CIN + ci]);
            float sb, cb;
            __sincosf(beta[co * CIN + ci], &sb, &cb);
            const float Wr = a * cb, Wi = a * sb;
            const float Zr = sZr[k * CIN + ci];
            const float Zi = sZi[k * CIN + ci];
            Gr += Wr * Zr - Wi * Zi;
            Gi += Wr * Zi + Wi * Zr;
        }
        const float mag  = sqrtf(Gr * Gr + Gi * Gi);
        const float gate = (1.f / (1.f + __expf(-(mag + bias[co])))) / (mag + 1e-5f);
        g_Gr[tid] = gate * Gr;
        g_Gi[tid] = gate * Gi;
        __syncthreads();
        if (tid == 0) {
            __threadfence();                   // publish G before releasing
            atomicAdd(&g_flag, 1);
        }
    } else if (tid == 0) {
        // -------- Everyone else: spin until G is published --------
        while (*((volatile int*)&g_flag) == s_init) { }
    }
    __syncthreads();
    __threadfence();                            // acquire G

    // ---------------- Phase B: stream the output ----------------
    // block -> output row b. out_r = Gr*c + Gi*s ; out_i = Gi*c - Gr*s.
    const int b    = bx;
    const float gr = g_Gr[b];
    const float gi = g_Gi[b];

    float* outr = out + (size_t)b * NLEN;
    float* outi = out + (size_t)NB * NLEN + (size_t)b * NLEN;

#pragma unroll
    for (int j = 0; j < 4; j++) {
        const int mu0 = j * 1024 + tid * 4;
        const float4 c4 = *reinterpret_cast<const float4*>(&g_cos[mu0]);
        const float4 s4 = *reinterpret_cast<const float4*>(&g_sin[mu0]);

        float4 vr, vi;
        vr.x = gr * c4.x + gi * s4.x;  vi.x = gi * c4.x - gr * s4.x;
        vr.y = gr * c4.y + gi * s4.y;  vi.y = gi * c4.y - gr * s4.y;
        vr.z = gr * c4.z + gi * s4.z;  vi.z = gi * c4.z - gr * s4.z;
        vr.w = gr * c4.w + gi * s4.w;  vi.w = gi * c4.w - gr * s4.w;

        *reinterpret_cast<float4*>(outr + mu0) = vr;
        *reinterpret_cast<float4*>(outi + mu0) = vi;
    }
}

extern "C" void kernel_launch(void* const* d_in, const int* in_sizes, int n_in,
                              void* d_out, int out_size)
{
    const float* z_real = (const float*)d_in[0];
    const float* z_imag = (const float*)d_in[1];
    const float* A      = (const float*)d_in[2];
    const float* beta   = (const float*)d_in[3];
    const float* bias   = (const float*)d_in[4];
    const int*   mptr   = (const int*)d_in[5];
    float* out = (float*)d_out;

    fused_kernel<<<NBLK, 256>>>(z_real, z_imag, A, beta, bias, mptr, out);
}

// round 14
// speedup vs baseline: 1.3372x; 1.0291x over previous
#include <cuda_runtime.h>
#include <math.h>

// Shapes fixed by the problem instance
#define KB    4
#define CIN   8
#define COUT  64
#define NLEN  4096
#define NROWS (KB * CIN)      // 32 input rows
#define SPLIT 2               // DFT blocks per input row (half-rows)
#define NDFT  (NROWS * SPLIT) // 64 DFT blocks
#define NTAB  16              // table blocks
#define NB    (KB * COUT)     // 256 output rows
#define NBLK  256             // total grid == NB (all co-resident)
#define TWO_PI_OVER_N 0.0015339807878856412f   // 2*pi/4096

// Scratch
__device__ float    g_part_r[NROWS][SPLIT];
__device__ float    g_part_i[NROWS][SPLIT];
__device__ float    g_cos[NLEN];
__device__ float    g_sin[NLEN];
__device__ int      g_count = 0;
__device__ unsigned g_flag  = 0;   // generation counter (sense-reversal)

__global__ __launch_bounds__(256) void fused_kernel(
    const float* __restrict__ zr, const float* __restrict__ zi,
    const float* __restrict__ A, const float* __restrict__ beta,
    const float* __restrict__ bias, const int* __restrict__ mptr,
    float* __restrict__ out)
{
    const int tid = threadIdx.x;
    const int bx  = blockIdx.x;

    __shared__ unsigned s_init;
    __shared__ int      s_last;
    __shared__ float    swr[8], swi[8];
    __shared__ float    sG[2];

    if (tid == 0) {
        s_init = *((volatile unsigned*)&g_flag);  // snapshot before own arrival
        s_last = 0;
    }
    __syncthreads();

    const int m = *mptr;

    // ---------------- Phase A ----------------
    if (bx < NDFT) {
        // Partial DFT: row b, half 'split', 8 consecutive samples per thread.
        // 2 sincosf + 7 complex rotations (MUFU throughput is precious).
        const int b     = bx >> 1;
        const int split = bx & 1;
        const int base  = split * 2048 + tid * 8;
        const float* pr = zr + (size_t)b * NLEN + base;
        const float* pi = zi + (size_t)b * NLEN + base;

        const float4 xa = *reinterpret_cast<const float4*>(pr);
        const float4 xb = *reinterpret_cast<const float4*>(pr + 4);
        const float4 ya = *reinterpret_cast<const float4*>(pi);
        const float4 yb = *reinterpret_cast<const float4*>(pi + 4);
        const float xs[8] = {xa.x, xa.y, xa.z, xa.w, xb.x, xb.y, xb.z, xb.w};
        const float ys[8] = {ya.x, ya.y, ya.z, ya.w, yb.x, yb.y, yb.z, yb.w};

        float s0, c0, s1, c1;
        {
            const int p0 = (m * base) & (NLEN - 1);    // exact start phase
            __sincosf(TWO_PI_OVER_N * (float)p0, &s0, &c0);
            const int p1 = m & (NLEN - 1);             // exact step phase
            __sincosf(TWO_PI_OVER_N * (float)p1, &s1, &c1);
        }

        float ar = 0.f, ai = 0.f;
        float c = c0, s = s0;
#pragma unroll
        for (int j = 0; j < 8; j++) {
            ar += xs[j] * c - ys[j] * s;               // e^{+i*omega*t} * z
            ai += xs[j] * s + ys[j] * c;
            const float cn = c * c1 - s * s1;          // rotate by e^{i*omega}
            const float sn = c * s1 + s * c1;
            c = cn; s = sn;
        }

#pragma unroll
        for (int off = 16; off > 0; off >>= 1) {
            ar += __shfl_down_sync(0xffffffff, ar, off);
            ai += __shfl_down_sync(0xffffffff, ai, off);
        }
        if ((tid & 31) == 0) { swr[tid >> 5] = ar; swi[tid >> 5] = ai; }
        __syncthreads();
        if (tid == 0) {
            float tr = 0.f, ti = 0.f;
#pragma unroll
            for (int w = 0; w < 8; w++) { tr += swr[w]; ti += swi[w]; }
            g_part_r[b][split] = tr;
            g_part_i[b][split] = ti;
        }
    } else if (bx < NDFT + NTAB) {
        // Phase table: components of e^{i*omega*mu}, exact arg reduction.
        const int mu = (bx - NDFT) * 256 + tid;
        const int p  = (m * mu) & (NLEN - 1);
        float s, c;
        __sincosf(TWO_PI_OVER_N * (float)p, &s, &c);
        g_cos[mu] = c;
        g_sin[mu] = s;
    }

    // ------------- Grid barrier: release on the 256th arrival -------------
    __syncthreads();
    if (tid == 0) {
        __threadfence();                        // publish partials / table
        int old = atomicAdd(&g_count, 1);
        if (old == NBLK - 1) {
            s_last = 1;
            atomicExch(&g_count, 0);            // reset for next graph replay
            atomicAdd(&g_flag, 1);              // immediate release
        }
    }
    __syncthreads();
    if (!s_last && tid == 0) {
        while (*((volatile unsigned*)&g_flag) == s_init) { }
    }
    __syncthreads();
    __threadfence();                            // acquire partials

    // ------------- Per-block G (warp 0): W*(Z0+Z1) folded per partial -------------
    const int k  = bx >> 6;
    const int co = bx & 63;
    if (tid < 32) {
        const int ci = tid & 7;
        const int sp = (tid >> 3) & 1;          // lanes 0-15 cover (ci,sp); 16-31 duplicate
        const int row = k * CIN + ci;
        const float Zr = g_part_r[row][sp];
        const float Zi = g_part_i[row][sp];
        const float a  = fabsf(A[co * CIN + ci]);
        float sb, cb;
        __sincosf(beta[co * CIN + ci], &sb, &cb);
        const float Wr = a * cb, Wi = a * sb;
        float Gr = Wr * Zr - Wi * Zi;
        float Gi = Wr * Zi + Wi * Zr;
#pragma unroll
        for (int off = 1; off < 16; off <<= 1) { // reduce within each 16-lane group
            Gr += __shfl_xor_sync(0xffffffff, Gr, off);
            Gi += __shfl_xor_sync(0xffffffff, Gi, off);
        }
        if (tid == 0) {
            const float mag  = sqrtf(Gr * Gr + Gi * Gi);
            const float gate = (1.f / (1.f + __expf(-(mag + bias[co])))) / (mag + 1e-5f);
            sG[0] = gate * Gr;
            sG[1] = gate * Gi;
        }
    }
    __syncthreads();

    // ---------------- Phase B: stream the output ----------------
    const float gr = sG[0];
    const float gi = sG[1];
    float* outr = out + (size_t)bx * NLEN;
    float* outi = out + (size_t)NB * NLEN + (size_t)bx * NLEN;

#pragma unroll
    for (int j = 0; j < 4; j++) {
        const int mu0 = j * 1024 + tid * 4;
        const float4 c4 = *reinterpret_cast<const float4*>(&g_cos[mu0]);
        const float4 s4 = *reinterpret_cast<const float4*>(&g_sin[mu0]);

        float4 vr, vi;
        vr.x = gr * c4.x + gi * s4.x;  vi.x = gi * c4.x - gr * s4.x;
        vr.y = gr * c4.y + gi * s4.y;  vi.y = gi * c4.y - gr * s4.y;
        vr.z = gr * c4.z + gi * s4.z;  vi.z = gi * c4.z - gr * s4.z;
        vr.w = gr * c4.w + gi * s4.w;  vi.w = gi * c4.w - gr * s4.w;

        *reinterpret_cast<float4*>(outr + mu0) = vr;
        *reinterpret_cast<float4*>(outi + mu0) = vi;
    }
}

extern "C" void kernel_launch(void* const* d_in, const int* in_sizes, int n_in,
                              void* d_out, int out_size)
{
    const float* z_real = (const float*)d_in[0];
    const float* z_imag = (const float*)d_in[1];
    const float* A      = (const float*)d_in[2];
    const float* beta   = (const float*)d_in[3];
    const float* bias   = (const float*)d_in[4];
    const int*   mptr   = (const int*)d_in[5];
    float* out = (float*)d_out;

    fused_kernel<<<NBLK, 256>>>(z_real, z_imag, A, beta, bias, mptr, out);
}

// round 15
// speedup vs baseline: 1.6912x; 1.2647x over previous
#include <cuda_runtime.h>
#include <math.h>

// Shapes fixed by the problem instance
#define KB    4
#define CIN   8
#define COUT  64
#define NLEN  4096
#define NROWS (KB * CIN)      // 32 input rows
#define SPLIT 2               // DFT blocks per input row (half-rows)
#define NDFT  (NROWS * SPLIT) // 64 DFT blocks
#define NTAB  16              // table blocks
#define NB    (KB * COUT)     // 256 output rows
#define NBLK  256             // total grid == NB (all co-resident)
#define TWO_PI_OVER_N 0.0015339807878856412f   // 2*pi/4096

// Scratch
__device__ float    g_part_r[NROWS][SPLIT];
__device__ float    g_part_i[NROWS][SPLIT];
__device__ float    g_cos[NLEN];
__device__ float    g_sin[NLEN];
__device__ int      g_count = 0;
__device__ unsigned g_flag  = 0;   // generation counter

__global__ __launch_bounds__(256) void fused_kernel(
    const float* __restrict__ zr, const float* __restrict__ zi,
    const float* __restrict__ A, const float* __restrict__ beta,
    const float* __restrict__ bias, const int* __restrict__ mptr,
    float* __restrict__ out)
{
    const int tid  = threadIdx.x;
    const int bx   = blockIdx.x;
    const int lane = tid & 31;

    __shared__ float swr[8], swi[8];

    // tid-0 snapshot of the generation BEFORE this block can possibly arrive.
    unsigned my_init = 0;
    if (tid == 0) my_init = *((volatile unsigned*)&g_flag);

    // ---- Pre-barrier W hoist (independent of partials; overlaps Phase A) ----
    // Per warp (redundant across warps): lanes map (ci, sp); lanes 16-31 mirror.
    const int k  = bx >> 6;
    const int co = bx & 63;
    const int ci = lane & 7;
    const int sp = (lane >> 3) & 1;
    float Wr, Wi;
    {
        const float a = fabsf(A[co * CIN + ci]);
        float sb, cb;
        __sincosf(beta[co * CIN + ci], &sb, &cb);
        Wr = a * cb; Wi = a * sb;
    }
    const float bco = bias[co];

    // ---------------- Phase A (producers only) ----------------
    if (bx < NDFT) {
        const int m     = *mptr;
        const int b     = bx >> 1;
        const int split = bx & 1;
        const int base  = split * 2048 + tid * 8;
        const float* pr = zr + (size_t)b * NLEN + base;
        const float* pi = zi + (size_t)b * NLEN + base;

        const float4 xa = *reinterpret_cast<const float4*>(pr);
        const float4 xb = *reinterpret_cast<const float4*>(pr + 4);
        const float4 ya = *reinterpret_cast<const float4*>(pi);
        const float4 yb = *reinterpret_cast<const float4*>(pi + 4);
        const float xs[8] = {xa.x, xa.y, xa.z, xa.w, xb.x, xb.y, xb.z, xb.w};
        const float ys[8] = {ya.x, ya.y, ya.z, ya.w, yb.x, yb.y, yb.z, yb.w};

        // 2 sincosf + 7 complex rotations (exact phase indices).
        float s0, c0, s1, c1;
        {
            const int p0 = (m * base) & (NLEN - 1);
            __sincosf(TWO_PI_OVER_N * (float)p0, &s0, &c0);
            const int p1 = m & (NLEN - 1);
            __sincosf(TWO_PI_OVER_N * (float)p1, &s1, &c1);
        }

        float ar = 0.f, ai = 0.f;
        float c = c0, s = s0;
#pragma unroll
        for (int j = 0; j < 8; j++) {
            ar += xs[j] * c - ys[j] * s;               // e^{+i*omega*t} * z
            ai += xs[j] * s + ys[j] * c;
            const float cn = c * c1 - s * s1;          // rotate by e^{i*omega}
            const float sn = c * s1 + s * c1;
            c = cn; s = sn;
        }

#pragma unroll
        for (int off = 16; off > 0; off >>= 1) {
            ar += __shfl_down_sync(0xffffffff, ar, off);
            ai += __shfl_down_sync(0xffffffff, ai, off);
        }
        if (lane == 0) { swr[tid >> 5] = ar; swi[tid >> 5] = ai; }
        __syncthreads();
        if (tid == 0) {
            float tr = 0.f, ti = 0.f;
#pragma unroll
            for (int w = 0; w < 8; w++) { tr += swr[w]; ti += swi[w]; }
            g_part_r[b][split] = tr;
            g_part_i[b][split] = ti;
        }
    } else if (bx < NDFT + NTAB) {
        // Phase table: components of e^{i*omega*mu}, exact arg reduction.
        const int m  = *mptr;
        const int mu = (bx - NDFT) * 256 + tid;
        const int p  = (m * mu) & (NLEN - 1);
        float s, c;
        __sincosf(TWO_PI_OVER_N * (float)p, &s, &c);
        g_cos[mu] = c;
        g_sin[mu] = s;
        __syncthreads();                                // uniform arrival point
    } else {
        __syncthreads();                                // consumers: arrive fast
    }

    // ------------- Grid barrier: all 256 arrive, last releases -------------
    if (tid == 0) {
        __threadfence();                        // publish partials / table
        int old = atomicAdd(&g_count, 1);
        if (old == NBLK - 1) {
            atomicExch(&g_count, 0);            // reset for next graph replay
            atomicAdd(&g_flag, 1);              // release (spin below exits at once)
        }
        while (*((volatile unsigned*)&g_flag) == my_init) { }
    }
    __syncthreads();
    __threadfence();                            // acquire partials + table

    // ------------- Warp-redundant G: every warp, all lanes end with G -------------
    float Gr, Gi;
    {
        const int row = k * CIN + ci;
        const float Zr = g_part_r[row][sp];
        const float Zi = g_part_i[row][sp];
        Gr = Wr * Zr - Wi * Zi;
        Gi = Wr * Zi + Wi * Zr;
#pragma unroll
        for (int off = 1; off < 16; off <<= 1) {
            Gr += __shfl_xor_sync(0xffffffff, Gr, off);
            Gi += __shfl_xor_sync(0xffffffff, Gi, off);
        }
    }
    const float mag  = sqrtf(Gr * Gr + Gi * Gi);
    const float gate = (1.f / (1.f + __expf(-(mag + bco)))) / (mag + 1e-5f);
    const float gr = gate * Gr;
    const float gi = gate * Gi;

    // ---------------- Phase B: stream the output ----------------
    float* outr = out + (size_t)bx * NLEN;
    float* outi = out + (size_t)NB * NLEN + (size_t)bx * NLEN;

#pragma unroll
    for (int j = 0; j < 4; j++) {
        const int mu0 = j * 1024 + tid * 4;
        const float4 c4 = *reinterpret_cast<const float4*>(&g_cos[mu0]);
        const float4 s4 = *reinterpret_cast<const float4*>(&g_sin[mu0]);

        float4 vr, vi;
        vr.x = gr * c4.x + gi * s4.x;  vi.x = gi * c4.x - gr * s4.x;
        vr.y = gr * c4.y + gi * s4.y;  vi.y = gi * c4.y - gr * s4.y;
        vr.z = gr * c4.z + gi * s4.z;  vi.z = gi * c4.z - gr * s4.z;
        vr.w = gr * c4.w + gi * s4.w;  vi.w = gi * c4.w - gr * s4.w;

        *reinterpret_cast<float4*>(outr + mu0) = vr;
        *reinterpret_cast<float4*>(outi + mu0) = vi;
    }
}

extern "C" void kernel_launch(void* const* d_in, const int* in_sizes, int n_in,
                              void* d_out, int out_size)
{
    const float* z_real = (const float*)d_in[0];
    const float* z_imag = (const float*)d_in[1];
    const float* A      = (const float*)d_in[2];
    const float* beta   = (const float*)d_in[3];
    const float* bias   = (const float*)d_in[4];
    const int*   mptr   = (const int*)d_in[5];
    float* out = (float*)d_out;

    fused_kernel<<<NBLK, 256>>>(z_real, z_imag, A, beta, bias, mptr, out);
}